// round 2
// baseline (speedup 1.0000x reference)
#include <cuda_runtime.h>

// AlignBlock on sm_103a, round 2: packed f32x2 FFMA throughout + smem-tiled
// conv/softmax. Shapes: B=2, C=H=64, T=512, F=64, DMAX=32. All fp32.

#define Bn 2
#define Cn 64
#define Hn 64
#define Tn 512
#define Fn 64
#define Dn 32

typedef unsigned long long u64;

__device__ __forceinline__ u64 pack2(float lo, float hi) {
    u64 r; asm("mov.b64 %0,{%1,%2};" : "=l"(r) : "f"(lo), "f"(hi)); return r;
}
__device__ __forceinline__ u64 bcast2(float x) {
    u64 r; asm("mov.b64 %0,{%1,%1};" : "=l"(r) : "f"(x)); return r;
}
__device__ __forceinline__ void ffma2(u64& d, u64 a, u64 b) {
    asm("fma.rn.f32x2 %0,%1,%2,%0;" : "+l"(d) : "l"(a), "l"(b));
}
__device__ __forceinline__ float2 unpack2(u64 v) {
    float lo, hi; asm("mov.b64 {%0,%1},%2;" : "=f"(lo), "=f"(hi) : "l"(v));
    return make_float2(lo, hi);
}

// Scratch
__device__ float g_Q[Bn * Hn * Tn * Fn];
__device__ float g_K[Bn * Hn * Tn * Fn];
__device__ float g_V[Bn * Hn * Tn * Dn];
__device__ float g_A[Bn * Tn * Dn];

// ---------------------------------------------------------------------------
// Kernel 1: channel mix for Q AND K in one launch.
// out[b,h,t,f] = sum_c w[h,c] * x[b,c,t,f] + bias[h]
// grid = 2 * B * (T/2) = 1024 blocks, 256 threads. Block: (which, b, 2 t's).
// Thread tile: 4h x 8f, f32x2 over f. FFMA2-pipe bound.
// ---------------------------------------------------------------------------
__global__ void __launch_bounds__(256) k_chanmix2(const float* __restrict__ xm,
                                                  const float* __restrict__ wm,
                                                  const float* __restrict__ bm,
                                                  const float* __restrict__ xr,
                                                  const float* __restrict__ wr,
                                                  const float* __restrict__ br) {
    const int tid = threadIdx.x;
    const int which = blockIdx.x >> 9;
    const int rem = blockIdx.x & 511;
    const int b = rem >> 8;
    const int t0 = (rem & 255) * 2;

    const float* x    = which ? xr : xm;
    const float* w    = which ? wr : wm;
    const float* bias = which ? br : bm;
    float* out        = which ? g_K : g_Q;

    __shared__ float xs[2][64][64];   // [ti][c][f]
    __shared__ float ws[64][64];      // [h][c]

#pragma unroll
    for (int it = 0; it < 16; it++) {
        int idx = tid + it * 256;
        ws[idx >> 6][idx & 63] = w[idx];
    }
#pragma unroll
    for (int it = 0; it < 8; it++) {
        int idx = tid + it * 256;              // float4 index 0..2047
        int f4 = (idx & 15) * 4;
        int c  = (idx >> 4) & 63;
        int ti = idx >> 10;
        *(float4*)&xs[ti][c][f4] =
            *(const float4*)&x[((b * 64 + c) * 512 + t0 + ti) * 64 + f4];
    }
    __syncthreads();

    const int ti = tid >> 7;
    const int l  = tid & 127;
    const int h0 = (l >> 3) * 4;
    const int f0 = (l & 7) * 8;

    u64 acc[4][4];
#pragma unroll
    for (int a = 0; a < 4; a++)
#pragma unroll
        for (int p = 0; p < 4; p++) acc[a][p] = 0ULL;

#pragma unroll 4
    for (int c = 0; c < 64; c++) {
        float4 x0 = *(const float4*)&xs[ti][c][f0];
        float4 x1 = *(const float4*)&xs[ti][c][f0 + 4];
        u64 xp0 = pack2(x0.x, x0.y);
        u64 xp1 = pack2(x0.z, x0.w);
        u64 xp2 = pack2(x1.x, x1.y);
        u64 xp3 = pack2(x1.z, x1.w);
#pragma unroll
        for (int a = 0; a < 4; a++) {
            u64 wb = bcast2(ws[h0 + a][c]);
            ffma2(acc[a][0], wb, xp0);
            ffma2(acc[a][1], wb, xp1);
            ffma2(acc[a][2], wb, xp2);
            ffma2(acc[a][3], wb, xp3);
        }
    }

#pragma unroll
    for (int a = 0; a < 4; a++) {
        float bb = __ldg(&bias[h0 + a]);
        float2 v0 = unpack2(acc[a][0]), v1 = unpack2(acc[a][1]);
        float2 v2 = unpack2(acc[a][2]), v3 = unpack2(acc[a][3]);
        float4 r0 = make_float4(v0.x + bb, v0.y + bb, v1.x + bb, v1.y + bb);
        float4 r1 = make_float4(v2.x + bb, v2.y + bb, v3.x + bb, v3.y + bb);
        float* og = &out[((b * 64 + h0 + a) * 512 + t0 + ti) * 64 + f0];
        *(float4*)og = r0;
        *(float4*)(og + 4) = r1;
    }
}

// ---------------------------------------------------------------------------
// Kernel 2: banded correlation, f32x2 over the t dimension.
// V[b,h,t,d] = (1/8) * sum_f Q[b,h,t,f] * K[b,h,t-31+d,f]
// grid = B*H*(T/64) = 1024 blocks, 128 threads.
// Thread tile: 4 t (as 2 pairs) x 4 d.
// ---------------------------------------------------------------------------
__global__ void __launch_bounds__(128) k_corr() {
    const int tid = threadIdx.x;
    const int t0 = (blockIdx.x & 7) * 64;
    const int h  = (blockIdx.x >> 3) & 63;
    const int b  = blockIdx.x >> 9;

    __shared__ float Qs[64][68];    // [f][i]
    __shared__ float Ks[64][100];   // [f][r], r = t_global - (t0-31)

    const float* qg = g_Q + ((b * 64 + h) * 512 + t0) * 64;
    const float* kg = g_K + ((b * 64 + h) * 512) * 64;

    for (int idx = tid; idx < 64 * 64; idx += 128) {
        int i = idx >> 6, f = idx & 63;
        Qs[f][i] = qg[i * 64 + f];
    }
    for (int idx = tid; idx < 95 * 64; idx += 128) {
        int r = idx >> 6, f = idx & 63;
        int tr = t0 - 31 + r;
        Ks[f][r] = (tr >= 0) ? kg[tr * 64 + f] : 0.0f;
    }
    __syncthreads();

    const int d0 = (tid & 7) * 4;
    const int i0 = (tid >> 3) * 4;

    u64 acc[4][2];   // [e = d offset][p = t pair]; lanes = t rows i0+2p, i0+2p+1
#pragma unroll
    for (int e = 0; e < 4; e++) { acc[e][0] = 0ULL; acc[e][1] = 0ULL; }

#pragma unroll 4
    for (int f = 0; f < 64; f++) {
        float4 q4 = *(const float4*)&Qs[f][i0];
        float4 k0 = *(const float4*)&Ks[f][i0 + d0];
        float4 k1 = *(const float4*)&Ks[f][i0 + d0 + 4];
        u64 qp0 = pack2(q4.x, q4.y);
        u64 qp1 = pack2(q4.z, q4.w);
        u64 P0 = pack2(k0.x, k0.y);
        u64 P1 = pack2(k0.y, k0.z);
        u64 P2 = pack2(k0.z, k0.w);
        u64 P3 = pack2(k0.w, k1.x);
        u64 P4 = pack2(k1.x, k1.y);
        u64 P5 = pack2(k1.y, k1.z);
        // acc[e][p] += qp[p] * P[e + 2p]   (k row for lane a,e is i0+d0+a+e)
        ffma2(acc[0][0], qp0, P0); ffma2(acc[0][1], qp1, P2);
        ffma2(acc[1][0], qp0, P1); ffma2(acc[1][1], qp1, P3);
        ffma2(acc[2][0], qp0, P2); ffma2(acc[2][1], qp1, P4);
        ffma2(acc[3][0], qp0, P3); ffma2(acc[3][1], qp1, P5);
    }

    float* vg = g_V + ((b * 64 + h) * 512 + t0) * 32;
#pragma unroll
    for (int p = 0; p < 2; p++) {
        float2 e0 = unpack2(acc[0][p]), e1 = unpack2(acc[1][p]);
        float2 e2 = unpack2(acc[2][p]), e3 = unpack2(acc[3][p]);
        float4 r0 = make_float4(e0.x * 0.125f, e1.x * 0.125f, e2.x * 0.125f, e3.x * 0.125f);
        float4 r1 = make_float4(e0.y * 0.125f, e1.y * 0.125f, e2.y * 0.125f, e3.y * 0.125f);
        *(float4*)&vg[(i0 + 2 * p) * 32 + d0] = r0;
        *(float4*)&vg[(i0 + 2 * p + 1) * 32 + d0] = r1;
    }
}

// ---------------------------------------------------------------------------
// Kernel 3: (5,3) conv over (T,dmax) reducing H->1, + softmax over dmax.
// Vc[b,t,d] = sum_h sum_{i,j} V[b,h,t-4+i,d-1+j] * w[h,i,j]   (bias dropped:
// uniform shift is softmax-invariant). A = softmax(Vc, axis=d).
// grid = B * (T/8) = 128 blocks, 128 threads. Thread = (t_local, d pair).
// V tile staged in smem per 16-h chunk, d padded both sides for the taps.
// ---------------------------------------------------------------------------
__global__ void __launch_bounds__(128) k_convsoftmax(const float* __restrict__ wconv) {
    const int tid = threadIdx.x;
    const int b  = blockIdx.x >> 6;
    const int t0 = (blockIdx.x & 63) * 8;

    __shared__ float Vs[16][12][34];  // [h_local][row r: t0-4+r][1+d], pads at 0,33
    __shared__ float wcs[64][16];     // padded conv weights
    __shared__ float red[8][33];

    for (int idx = tid; idx < 960; idx += 128)
        wcs[idx / 15][idx % 15] = wconv[idx];
    for (int idx = tid; idx < 16 * 12; idx += 128) {
        Vs[idx / 12][idx % 12][0]  = 0.0f;
        Vs[idx / 12][idx % 12][33] = 0.0f;
    }

    const int tl = tid >> 4;        // 0..7
    const int d  = (tid & 15) * 2;  // even

    float accA0 = 0.f, accA1 = 0.f, accB0 = 0.f, accB1 = 0.f;

    for (int hc = 0; hc < 4; hc++) {
        __syncthreads();
        for (int g = tid; g < 1536; g += 128) {
            int dq = g & 7;
            int hr = g >> 3;
            int r  = hr % 12;
            int hl = hr / 12;
            int tt = t0 - 4 + r;
            float4 v = make_float4(0.f, 0.f, 0.f, 0.f);
            if (tt >= 0)
                v = *(const float4*)&g_V[((b * 64 + hc * 16 + hl) * 512 + tt) * 32 + dq * 4];
            Vs[hl][r][1 + dq * 4 + 0] = v.x;
            Vs[hl][r][1 + dq * 4 + 1] = v.y;
            Vs[hl][r][1 + dq * 4 + 2] = v.z;
            Vs[hl][r][1 + dq * 4 + 3] = v.w;
        }
        __syncthreads();

#pragma unroll 2
        for (int hl = 0; hl < 16; hl++) {
            int hh = hc * 16 + hl;
            float wreg[16];
#pragma unroll
            for (int k4 = 0; k4 < 4; k4++) {
                float4 wv = *(const float4*)&wcs[hh][k4 * 4];
                wreg[k4 * 4 + 0] = wv.x; wreg[k4 * 4 + 1] = wv.y;
                wreg[k4 * 4 + 2] = wv.z; wreg[k4 * 4 + 3] = wv.w;
            }
#pragma unroll
            for (int i = 0; i < 5; i++) {
                float2 u = *(const float2*)&Vs[hl][tl + i][d];
                float2 v = *(const float2*)&Vs[hl][tl + i][d + 2];
                float w0 = wreg[i * 3], w1 = wreg[i * 3 + 1], w2 = wreg[i * 3 + 2];
                if (i & 1) {
                    accB0 += u.x * w0 + u.y * w1 + v.x * w2;
                    accB1 += u.y * w0 + v.x * w1 + v.y * w2;
                } else {
                    accA0 += u.x * w0 + u.y * w1 + v.x * w2;
                    accA1 += u.y * w0 + v.x * w1 + v.y * w2;
                }
            }
        }
    }

    red[tl][d]     = accA0 + accB0;
    red[tl][d + 1] = accA1 + accB1;
    __syncthreads();

    const int wid = tid >> 5, lane = tid & 31;
#pragma unroll
    for (int rr = 0; rr < 2; rr++) {
        int row = wid * 2 + rr;
        float v = red[row][lane];
        float mx = v;
#pragma unroll
        for (int o = 16; o > 0; o >>= 1)
            mx = fmaxf(mx, __shfl_xor_sync(0xffffffffu, mx, o));
        float e = __expf(v - mx);
        float s = e;
#pragma unroll
        for (int o = 16; o > 0; o >>= 1)
            s += __shfl_xor_sync(0xffffffffu, s, o);
        g_A[(b * 512 + t0 + row) * 32 + lane] = e / s;
    }
}

// ---------------------------------------------------------------------------
// Kernel 4: aligned[b,c,t,f] = sum_d A[b,t,d] * x_ref[b,c,t-31+d,f]
// grid = B*C*(T/64) = 1024 blocks, 256 threads. Thread tile: 4t x 4f (2 pairs).
// ---------------------------------------------------------------------------
__global__ void __launch_bounds__(256) k_align(const float* __restrict__ xref,
                                               float* __restrict__ out) {
    const int tid = threadIdx.x;
    const int t0 = (blockIdx.x & 7) * 64;
    const int c  = (blockIdx.x >> 3) & 63;
    const int b  = blockIdx.x >> 9;

    __shared__ float As[64][36];    // [i][d]
    __shared__ float Xs[95][68];    // [r][f], r = t_global - (t0-31)

    const float* ag = g_A + (b * 512 + t0) * 32;
    const float* xg = xref + ((b * 64 + c) * 512) * 64;

    for (int idx = tid; idx < 64 * 32; idx += 256) {
        int i = idx >> 5, dd = idx & 31;
        As[i][dd] = ag[i * 32 + dd];
    }
    for (int idx = tid; idx < 95 * 64; idx += 256) {
        int r = idx >> 6, f = idx & 63;
        int tr = t0 - 31 + r;
        Xs[r][f] = (tr >= 0) ? xg[tr * 64 + f] : 0.0f;
    }
    __syncthreads();

    const int f0 = (tid & 15) * 4;
    const int i0 = (tid >> 4) * 4;

    u64 acc[4][2];   // [a = t row][p = f pair]
#pragma unroll
    for (int a = 0; a < 4; a++) { acc[a][0] = 0ULL; acc[a][1] = 0ULL; }

#pragma unroll 2
    for (int d0 = 0; d0 < 32; d0 += 4) {
        float4 av[4];
#pragma unroll
        for (int a = 0; a < 4; a++) av[a] = *(const float4*)&As[i0 + a][d0];
        u64 xp[7][2];
#pragma unroll
        for (int k = 0; k < 7; k++) {
            const float* xr = &Xs[i0 + d0 + k][f0];
            xp[k][0] = *(const u64*)xr;        // aligned (f0 % 4 == 0)
            xp[k][1] = *(const u64*)(xr + 2);
        }
#pragma unroll
        for (int a = 0; a < 4; a++) {
            float aa[4] = {av[a].x, av[a].y, av[a].z, av[a].w};
#pragma unroll
            for (int dd = 0; dd < 4; dd++) {
                u64 ab = bcast2(aa[dd]);
                ffma2(acc[a][0], ab, xp[a + dd][0]);
                ffma2(acc[a][1], ab, xp[a + dd][1]);
            }
        }
    }

    float* og = out + ((b * 64 + c) * 512 + t0) * 64;
#pragma unroll
    for (int a = 0; a < 4; a++) {
        float2 u0 = unpack2(acc[a][0]), u1 = unpack2(acc[a][1]);
        *(float4*)&og[(i0 + a) * 64 + f0] = make_float4(u0.x, u0.y, u1.x, u1.y);
    }
}

// ---------------------------------------------------------------------------
extern "C" void kernel_launch(void* const* d_in, const int* in_sizes, int n_in,
                              void* d_out, int out_size) {
    (void)in_sizes; (void)n_in; (void)out_size;
    const float* x_mic  = (const float*)d_in[0];
    const float* x_ref  = (const float*)d_in[1];
    const float* w_mic  = (const float*)d_in[2];
    const float* b_mic  = (const float*)d_in[3];
    const float* w_ref  = (const float*)d_in[4];
    const float* b_ref  = (const float*)d_in[5];
    const float* w_conv = (const float*)d_in[6];
    float* out = (float*)d_out;

    k_chanmix2<<<2 * Bn * (Tn / 2), 256>>>(x_mic, w_mic, b_mic, x_ref, w_ref, b_ref);
    k_corr<<<Bn * Hn * (Tn / 64), 128>>>();
    k_convsoftmax<<<Bn * (Tn / 8), 128>>>(w_conv);
    k_align<<<Bn * Cn * (Tn / 64), 256>>>(x_ref, out);
}